// round 5
// baseline (speedup 1.0000x reference)
#include <cuda_runtime.h>
#include <cuda_bf16.h>
#include <cuda_fp16.h>
#include <math.h>

#define N_NODES 100000
#define N_EDGES 1600000
#define NFEAT   256
#define NHID    64
#define NHEADS  8
#define NH_TOT  (NHEADS*NHID)   // 512
#define NCLASS  97
#define ALPHA   0.2f
#define EPSG    1e-16f

typedef unsigned long long ull;

// ---------------- device scratch (no allocs allowed) ----------------
__device__ __half g_hh  [(size_t)N_NODES * NH_TOT];   // layer1 hidden, fp16 (gather operand)
__device__ float g_x    [(size_t)N_NODES * NH_TOT];   // layer1 output (post elu)
__device__ float g_h2   [(size_t)N_NODES * NCLASS];   // layer2 hidden
__device__ float g_ssrc [(size_t)N_NODES * NHEADS];
__device__ float g_sdstT[(size_t)NHEADS * N_NODES];   // transposed: [head][node]
__device__ float g_s2src[N_NODES];
__device__ float g_s2dst[N_NODES];
__device__ int   g_counts[N_NODES];
__device__ int   g_fill  [N_NODES];
__device__ int   g_rowptr[N_NODES + 1];
__device__ int   g_csr   [N_EDGES];
__device__ int   g_partials[256];
__device__ int   g_is64;

// ---------------- f32x2 / bit-cast helpers ----------------
__device__ __forceinline__ ull pack2(float x, float y) {
    ull r; asm("mov.b64 %0, {%1, %2};" : "=l"(r) : "f"(x), "f"(y)); return r;
}
__device__ __forceinline__ float2 unpack2(ull v) {
    float2 r; asm("mov.b64 {%0, %1}, %2;" : "=f"(r.x), "=f"(r.y) : "l"(v)); return r;
}
__device__ __forceinline__ void ffma2(ull& d, ull a, ull b) {
    asm("fma.rn.f32x2 %0, %1, %2, %0;" : "+l"(d) : "l"(a), "l"(b));
}
__device__ __forceinline__ unsigned h2u(__half2 h) {
    unsigned r; memcpy(&r, &h, 4); return r;
}
__device__ __forceinline__ __half2 u2h(unsigned v) {
    __half2 h; memcpy(&h, &v, 4); return h;
}

// ---------------- edge index readers ----------------
__device__ __forceinline__ int edge_src(const void* ei, int e) {
    if (g_is64) return (int)((const long long*)ei)[e];
    return ((const int*)ei)[e];
}
__device__ __forceinline__ int edge_dst(const void* ei, int e) {
    if (g_is64) return (int)((const long long*)ei)[(size_t)N_EDGES + e];
    return ((const int*)ei)[(size_t)N_EDGES + e];
}

// ---------------- init / detect ----------------
__global__ void init_kernel() {
    int i = blockIdx.x * blockDim.x + threadIdx.x;
    if (i < N_NODES) { g_counts[i] = 0; g_fill[i] = 0; }
    if (i == 0) g_is64 = 1;
}

__global__ void detect_kernel(const int* __restrict__ w) {
    int i = blockIdx.x * blockDim.x + threadIdx.x;
    if (i < 4096) {
        if (w[2 * i + 1] != 0) g_is64 = 0;  // odd word nonzero => int32 data
    }
}

// ---------------- GEMM1 fused with s1, fp16 h output ----------------
// grid: (ceil(N/128), NHEADS); block 256. Tile 128 rows x 64 cols (full head).
// 8 rows x 4 cols per thread, f32x2 packed accumulators over row pairs.
__global__ __launch_bounds__(256) void gemm1_kernel(
    const float* __restrict__ A, const float* __restrict__ W,
    const float* __restrict__ a)
{
    __shared__ __align__(16) float As[16][132];  // [k][row]
    __shared__ __align__(16) float Bs[16][64];   // [k][col]
    const int head = blockIdx.y;
    const float* B = W + (size_t)head * NFEAT * NHID;
    const int row0 = blockIdx.x * 128;
    const int tx = threadIdx.x & 15, ty = threadIdx.x >> 4;

    ull acc[4][4];   // [row-pair i2][col j]; rows = ty*8 + 2*i2 + {0,1}, col = tx*4+j
#pragma unroll
    for (int i = 0; i < 4; i++)
#pragma unroll
        for (int j = 0; j < 4; j++) acc[i][j] = 0ull;

    for (int k0 = 0; k0 < NFEAT; k0 += 16) {
        // load A tile 128x16, transpose to As[k][r]
#pragma unroll
        for (int l = 0; l < 2; l++) {
            int idx = threadIdx.x + l * 256;        // 0..511
            int r = idx >> 2, kq = (idx & 3) * 4;
            float4 v = make_float4(0.f, 0.f, 0.f, 0.f);
            int gr = row0 + r;
            if (gr < N_NODES) v = *(const float4*)&A[(size_t)gr * NFEAT + k0 + kq];
            As[kq + 0][r] = v.x; As[kq + 1][r] = v.y;
            As[kq + 2][r] = v.z; As[kq + 3][r] = v.w;
        }
        // load B tile 16x64
        {
            int k = threadIdx.x >> 4, c4 = (threadIdx.x & 15) * 4;
            *(float4*)&Bs[k][c4] = *(const float4*)&B[(size_t)(k0 + k) * NHID + c4];
        }
        __syncthreads();
#pragma unroll
        for (int kk = 0; kk < 16; kk++) {
            ulonglong2 a01 = *(const ulonglong2*)&As[kk][ty * 8];
            ulonglong2 a23 = *(const ulonglong2*)&As[kk][ty * 8 + 4];
            float4 bv = *(const float4*)&Bs[kk][tx * 4];
            ull b0 = pack2(bv.x, bv.x), b1 = pack2(bv.y, bv.y);
            ull b2 = pack2(bv.z, bv.z), b3 = pack2(bv.w, bv.w);
            ffma2(acc[0][0], a01.x, b0); ffma2(acc[0][1], a01.x, b1);
            ffma2(acc[0][2], a01.x, b2); ffma2(acc[0][3], a01.x, b3);
            ffma2(acc[1][0], a01.y, b0); ffma2(acc[1][1], a01.y, b1);
            ffma2(acc[1][2], a01.y, b2); ffma2(acc[1][3], a01.y, b3);
            ffma2(acc[2][0], a23.x, b0); ffma2(acc[2][1], a23.x, b1);
            ffma2(acc[2][2], a23.x, b2); ffma2(acc[2][3], a23.x, b3);
            ffma2(acc[3][0], a23.y, b0); ffma2(acc[3][1], a23.y, b1);
            ffma2(acc[3][2], a23.y, b2); ffma2(acc[3][3], a23.y, b3);
        }
        __syncthreads();
    }

    // epilogue: unpack, store h (fp16), fused s1 partial reduction
    const float* ak = a + (size_t)head * 2 * NHID;
    float a1v[4], a2v[4];
#pragma unroll
    for (int j = 0; j < 4; j++) {
        a1v[j] = ak[tx * 4 + j];
        a2v[j] = ak[NHID + tx * 4 + j];
    }
    float psa[8], psb[8];
#pragma unroll
    for (int i2 = 0; i2 < 4; i2++) {
        float2 v0 = unpack2(acc[i2][0]);
        float2 v1 = unpack2(acc[i2][1]);
        float2 v2 = unpack2(acc[i2][2]);
        float2 v3 = unpack2(acc[i2][3]);
        int r0 = ty * 8 + 2 * i2, r1 = r0 + 1;
        float4 h0 = make_float4(v0.x, v1.x, v2.x, v3.x);
        float4 h1 = make_float4(v0.y, v1.y, v2.y, v3.y);
        if (row0 + r0 < N_NODES) {
            uint2 pk;
            pk.x = h2u(__floats2half2_rn(h0.x, h0.y));
            pk.y = h2u(__floats2half2_rn(h0.z, h0.w));
            *(uint2*)&g_hh[(size_t)(row0 + r0) * NH_TOT + head * NHID + tx * 4] = pk;
        }
        if (row0 + r1 < N_NODES) {
            uint2 pk;
            pk.x = h2u(__floats2half2_rn(h1.x, h1.y));
            pk.y = h2u(__floats2half2_rn(h1.z, h1.w));
            *(uint2*)&g_hh[(size_t)(row0 + r1) * NH_TOT + head * NHID + tx * 4] = pk;
        }
        psa[2 * i2]     = h0.x * a1v[0] + h0.y * a1v[1] + h0.z * a1v[2] + h0.w * a1v[3];
        psa[2 * i2 + 1] = h1.x * a1v[0] + h1.y * a1v[1] + h1.z * a1v[2] + h1.w * a1v[3];
        psb[2 * i2]     = h0.x * a2v[0] + h0.y * a2v[1] + h0.z * a2v[2] + h0.w * a2v[3];
        psb[2 * i2 + 1] = h1.x * a2v[0] + h1.y * a2v[1] + h1.z * a2v[2] + h1.w * a2v[3];
    }
#pragma unroll
    for (int r = 0; r < 8; r++) {
#pragma unroll
        for (int o = 8; o; o >>= 1) {
            psa[r] += __shfl_xor_sync(0xffffffffu, psa[r], o, 16);
            psb[r] += __shfl_xor_sync(0xffffffffu, psb[r], o, 16);
        }
    }
    if (tx == 0) {
#pragma unroll
        for (int r = 0; r < 8; r++) {
            int gr = row0 + ty * 8 + r;
            if (gr < N_NODES) {
                g_ssrc[(size_t)gr * NHEADS + head] = psa[r];
                g_sdstT[(size_t)head * N_NODES + gr] = psb[r];
            }
        }
    }
}

// ---------------- CSR build ----------------
__global__ void hist_kernel(const void* __restrict__ ei) {
    int e = blockIdx.x * blockDim.x + threadIdx.x;
    if (e >= N_EDGES) return;
    atomicAdd(&g_counts[edge_src(ei, e)], 1);
}

__global__ void chunk_sums_kernel() {
    __shared__ int sh[512];
    int i = blockIdx.x * 512 + threadIdx.x;
    sh[threadIdx.x] = (i < N_NODES) ? g_counts[i] : 0;
    __syncthreads();
#pragma unroll
    for (int s = 256; s > 0; s >>= 1) {
        if (threadIdx.x < s) sh[threadIdx.x] += sh[threadIdx.x + s];
        __syncthreads();
    }
    if (threadIdx.x == 0) g_partials[blockIdx.x] = sh[0];
}

__global__ void scan_partials_kernel(int n) {
    __shared__ int sh[256];
    int v = (threadIdx.x < n) ? g_partials[threadIdx.x] : 0;
    sh[threadIdx.x] = v;
    __syncthreads();
#pragma unroll
    for (int d = 1; d < 256; d <<= 1) {
        int t = (threadIdx.x >= d) ? sh[threadIdx.x - d] : 0;
        __syncthreads();
        sh[threadIdx.x] += t;
        __syncthreads();
    }
    if (threadIdx.x < n) g_partials[threadIdx.x] = sh[threadIdx.x] - v;  // exclusive
}

__global__ void scan_chunks_kernel() {
    __shared__ int sh[512];
    int i = blockIdx.x * 512 + threadIdx.x;
    int v = (i < N_NODES) ? g_counts[i] : 0;
    sh[threadIdx.x] = v;
    __syncthreads();
#pragma unroll
    for (int d = 1; d < 512; d <<= 1) {
        int t = (threadIdx.x >= d) ? sh[threadIdx.x - d] : 0;
        __syncthreads();
        sh[threadIdx.x] += t;
        __syncthreads();
    }
    int incl = sh[threadIdx.x];
    if (i < N_NODES) g_rowptr[i] = g_partials[blockIdx.x] + incl - v;
    if (i == N_NODES - 1) g_rowptr[N_NODES] = g_partials[blockIdx.x] + incl;
}

__global__ void scatter_kernel(const void* __restrict__ ei) {
    int e = blockIdx.x * blockDim.x + threadIdx.x;
    if (e >= N_EDGES) return;
    int s = edge_src(ei, e);
    int d = edge_dst(ei, e);
    int pos = g_rowptr[s] + atomicAdd(&g_fill[s], 1);
    g_csr[pos] = d;
}

// ---------------- agg1: per (node, head) aggregation, fp16 gather ----
// warp per node; lane covers cols {2*lane, 2*lane+1} of the 64-wide head slice.
__global__ __launch_bounds__(256) void agg1_kernel() {
    int lane = threadIdx.x & 31;
    int n = blockIdx.x * 8 + (threadIdx.x >> 5);
    if (n >= N_NODES) return;
    int k = blockIdx.y;
    int beg = g_rowptr[n], end = g_rowptr[n + 1];
    float ssrc = g_ssrc[(size_t)n * NHEADS + k];
    const float* sdT = g_sdstT + (size_t)k * N_NODES;
    const unsigned* hhw = (const unsigned*)g_hh;   // half2 view: 256 uints per node
    float accx = 0.f, accy = 0.f, rs = 0.f;

    for (int c0 = beg; c0 < end; c0 += 32) {
        int m = end - c0; if (m > 32) m = 32;
        int dst = 0; float e = 0.f;
        if (lane < m) {
            dst = g_csr[c0 + lane];
            float z = ssrc + sdT[dst];
            float lr = fmaxf(z, ALPHA * z);
            e = __expf(-lr);
        }
#pragma unroll 4
        for (int j = 0; j < m; j++) {
            float ej = __shfl_sync(0xffffffffu, e, j);
            int   dj = __shfl_sync(0xffffffffu, dst, j);
            unsigned hv = hhw[(size_t)dj * 256 + k * 32 + lane];
            float2 f = __half22float2(u2h(hv));
            accx += ej * f.x;
            accy += ej * f.y;
            rs += ej;
        }
    }
    float inv = 1.f / (rs + EPSG);
    float v0 = accx * inv, v1 = accy * inv;
    v0 = (v0 > 0.f) ? v0 : expm1f(v0);
    v1 = (v1 > 0.f) ? v1 : expm1f(v1);
    *(float2*)&g_x[(size_t)n * NH_TOT + k * NHID + 2 * lane] = make_float2(v0, v1);
}

// ---------------- GEMM2: h2 = x @ W_out (512 -> 97), f32x2 packed ----------------
__global__ __launch_bounds__(256) void gemm2_kernel(const float* __restrict__ Wo) {
    __shared__ float xs[64][68];   // [k][row]
    int c = threadIdx.x;           // 0..127 (active < 97)
    int ty = threadIdx.y;          // 0..1
    int tid = ty * 128 + c;
    int row0 = blockIdx.x * 64;
    bool act = (c < NCLASS);

    ull acc[16];
#pragma unroll
    for (int m = 0; m < 16; m++) acc[m] = 0ull;

    for (int k0 = 0; k0 < NH_TOT; k0 += 64) {
#pragma unroll
        for (int l = 0; l < 4; l++) {
            int idx = tid + l * 256;       // 0..1023
            int r = idx & 63, q = idx >> 6; // q 0..15
            float4 v = make_float4(0.f, 0.f, 0.f, 0.f);
            if (row0 + r < N_NODES)
                v = *(const float4*)&g_x[(size_t)(row0 + r) * NH_TOT + k0 + q * 4];
            xs[q * 4 + 0][r] = v.x; xs[q * 4 + 1][r] = v.y;
            xs[q * 4 + 2][r] = v.z; xs[q * 4 + 3][r] = v.w;
        }
        __syncthreads();
#pragma unroll 4
        for (int k = 0; k < 64; k++) {
            float w = act ? Wo[(size_t)(k0 + k) * NCLASS + c] : 0.f;
            ull wp = pack2(w, w);
            const ulonglong2* xr = (const ulonglong2*)&xs[k][ty * 32];
#pragma unroll
            for (int m = 0; m < 8; m++) {
                ulonglong2 xv = xr[m];
                ffma2(acc[2 * m], xv.x, wp);
                ffma2(acc[2 * m + 1], xv.y, wp);
            }
        }
        __syncthreads();
    }
    if (act) {
#pragma unroll
        for (int m = 0; m < 16; m++) {
            float2 v = unpack2(acc[m]);
            int base = (m & 1) ? (ty * 32 + (m >> 1) * 4 + 2) : (ty * 32 + (m >> 1) * 4);
            int gr0 = row0 + base, gr1 = gr0 + 1;
            if (gr0 < N_NODES) g_h2[(size_t)gr0 * NCLASS + c] = v.x;
            if (gr1 < N_NODES) g_h2[(size_t)gr1 * NCLASS + c] = v.y;
        }
    }
}

// ---------------- s2: per-node dots with a_out halves ----------------
__global__ __launch_bounds__(256) void s2_kernel(const float* __restrict__ ao) {
    int lane = threadIdx.x & 31;
    int n = blockIdx.x * 8 + (threadIdx.x >> 5);
    if (n >= N_NODES) return;
    const float* hr = g_h2 + (size_t)n * NCLASS;
    float sa = 0.f, sb = 0.f;
#pragma unroll
    for (int q = 0; q < 4; q++) {
        int cc = lane + q * 32;
        if (cc < NCLASS) {
            float v = hr[cc];
            sa += v * ao[cc];
            sb += v * ao[NCLASS + cc];
        }
    }
#pragma unroll
    for (int o = 16; o; o >>= 1) {
        sa += __shfl_down_sync(0xffffffffu, sa, o);
        sb += __shfl_down_sync(0xffffffffu, sb, o);
    }
    if (lane == 0) { g_s2src[n] = sa; g_s2dst[n] = sb; }
}

// ---------------- agg2: aggregation + elu + log_softmax ----------------
__global__ __launch_bounds__(256) void agg2_kernel(float* __restrict__ out) {
    int lane = threadIdx.x & 31;
    int n = blockIdx.x * 8 + (threadIdx.x >> 5);
    if (n >= N_NODES) return;
    int beg = g_rowptr[n], end = g_rowptr[n + 1];
    float ssrc = g_s2src[n];
    float acc[4] = {0.f, 0.f, 0.f, 0.f};
    float rs = 0.f;

    for (int c0 = beg; c0 < end; c0 += 32) {
        int m = end - c0; if (m > 32) m = 32;
        int dst = 0; float e = 0.f;
        if (lane < m) {
            dst = g_csr[c0 + lane];
            float z = ssrc + g_s2dst[dst];
            float lr = fmaxf(z, ALPHA * z);
            e = __expf(-lr);
        }
#pragma unroll 2
        for (int j = 0; j < m; j++) {
            float ej = __shfl_sync(0xffffffffu, e, j);
            int   dj = __shfl_sync(0xffffffffu, dst, j);
            const float* hr = g_h2 + (size_t)dj * NCLASS;
#pragma unroll
            for (int q = 0; q < 4; q++) {
                int cc = lane + q * 32;
                if (cc < NCLASS) acc[q] += ej * hr[cc];
            }
            rs += ej;
        }
    }
    float inv = 1.f / (rs + EPSG);
    float v[4];
    float mx = -INFINITY;
#pragma unroll
    for (int q = 0; q < 4; q++) {
        int cc = lane + q * 32;
        if (cc < NCLASS) {
            float t = acc[q] * inv;
            t = (t > 0.f) ? t : expm1f(t);
            v[q] = t;
            mx = fmaxf(mx, t);
        } else v[q] = -INFINITY;
    }
#pragma unroll
    for (int o = 16; o; o >>= 1) mx = fmaxf(mx, __shfl_xor_sync(0xffffffffu, mx, o));
    float se = 0.f;
#pragma unroll
    for (int q = 0; q < 4; q++) {
        int cc = lane + q * 32;
        if (cc < NCLASS) se += __expf(v[q] - mx);
    }
#pragma unroll
    for (int o = 16; o; o >>= 1) se += __shfl_xor_sync(0xffffffffu, se, o);
    float lse = mx + logf(se);
#pragma unroll
    for (int q = 0; q < 4; q++) {
        int cc = lane + q * 32;
        if (cc < NCLASS) out[(size_t)n * NCLASS + cc] = v[q] - lse;
    }
}

// ---------------- launch ----------------
extern "C" void kernel_launch(void* const* d_in, const int* in_sizes, int n_in,
                              void* d_out, int out_size) {
    const float* features = (const float*)d_in[0];
    const float* W        = (const float*)d_in[1];
    const float* a        = (const float*)d_in[2];
    const float* W_out    = (const float*)d_in[3];
    const float* a_out    = (const float*)d_in[4];
    const void*  ei       = d_in[5];
    float* out            = (float*)d_out;

    init_kernel<<<(N_NODES + 255) / 256, 256>>>();
    detect_kernel<<<16, 256>>>((const int*)ei);

    gemm1_kernel<<<dim3((N_NODES + 127) / 128, NHEADS), 256>>>(features, W, a);

    hist_kernel<<<(N_EDGES + 255) / 256, 256>>>(ei);
    int nchunks = (N_NODES + 511) / 512;   // 196
    chunk_sums_kernel<<<nchunks, 512>>>();
    scan_partials_kernel<<<1, 256>>>(nchunks);
    scan_chunks_kernel<<<nchunks, 512>>>();
    scatter_kernel<<<(N_EDGES + 255) / 256, 256>>>(ei);

    agg1_kernel<<<dim3((N_NODES + 7) / 8, NHEADS), 256>>>();

    gemm2_kernel<<<(N_NODES + 63) / 64, dim3(128, 2)>>>(W_out);
    s2_kernel<<<(N_NODES + 7) / 8, 256>>>(a_out);
    agg2_kernel<<<(N_NODES + 7) / 8, 256>>>(out);
}

// round 9
// speedup vs baseline: 1.7991x; 1.7991x over previous
#include <cuda_runtime.h>
#include <cuda_bf16.h>
#include <math.h>
#include <string.h>

#define N_NODES 100000
#define N_EDGES 1600000
#define NFEAT   256
#define NHID    64
#define NHEADS  8
#define NH_TOT  (NHEADS*NHID)   // 512
#define NCLASS  97
#define ALPHA   0.2f
#define EPSG    1e-16f

typedef unsigned long long ull;
typedef unsigned int u32;

// ---------------- device scratch (no allocs allowed) ----------------
__device__ float g_h    [(size_t)N_NODES * NH_TOT];   // layer1 hidden (fp32)
__device__ float g_x    [(size_t)N_NODES * NH_TOT];   // layer1 output (post elu)
__device__ float g_h2   [(size_t)N_NODES * NCLASS];   // layer2 hidden
__device__ float g_ssrc [(size_t)N_NODES * NHEADS];
__device__ float g_sdstT[(size_t)NHEADS * N_NODES];   // transposed: [head][node]
__device__ float g_s2src[N_NODES];
__device__ float g_s2dst[N_NODES];
__device__ int   g_counts[N_NODES];
__device__ int   g_fill  [N_NODES];
__device__ int   g_rowptr[N_NODES + 1];
__device__ int   g_csr   [N_EDGES];
__device__ int   g_partials[256];
__device__ int   g_is64;

// ---------------- f32x2 helpers ----------------
__device__ __forceinline__ ull pack2(float x, float y) {
    ull r; asm("mov.b64 %0, {%1, %2};" : "=l"(r) : "f"(x), "f"(y)); return r;
}
__device__ __forceinline__ float2 unpack2(ull v) {
    float2 r; asm("mov.b64 {%0, %1}, %2;" : "=f"(r.x), "=f"(r.y) : "l"(v)); return r;
}
__device__ __forceinline__ void ffma2(ull& d, ull a, ull b) {
    asm("fma.rn.f32x2 %0, %1, %2, %0;" : "+l"(d) : "l"(a), "l"(b));
}

// ---------------- mma.sync bf16 helper (baseline PTX, works on sm_103) ------
__device__ __forceinline__ void mma16816(float* d, const u32* a, const u32* b) {
    asm volatile(
        "mma.sync.aligned.m16n8k16.row.col.f32.bf16.bf16.f32 "
        "{%0,%1,%2,%3}, {%4,%5,%6,%7}, {%8,%9}, {%0,%1,%2,%3};"
        : "+f"(d[0]), "+f"(d[1]), "+f"(d[2]), "+f"(d[3])
        : "r"(a[0]), "r"(a[1]), "r"(a[2]), "r"(a[3]), "r"(b[0]), "r"(b[1]));
}

// ---------------- edge index readers ----------------
__device__ __forceinline__ int edge_src(const void* ei, int e) {
    if (g_is64) return (int)((const long long*)ei)[e];
    return ((const int*)ei)[e];
}
__device__ __forceinline__ int edge_dst(const void* ei, int e) {
    if (g_is64) return (int)((const long long*)ei)[(size_t)N_EDGES + e];
    return ((const int*)ei)[(size_t)N_EDGES + e];
}

// ---------------- init / detect ----------------
__global__ void init_kernel() {
    int i = blockIdx.x * blockDim.x + threadIdx.x;
    if (i < N_NODES) { g_counts[i] = 0; g_fill[i] = 0; }
    if (i == 0) g_is64 = 1;
}

__global__ void detect_kernel(const int* __restrict__ w) {
    int i = blockIdx.x * blockDim.x + threadIdx.x;
    if (i < 4096) {
        if (w[2 * i + 1] != 0) g_is64 = 0;  // odd word nonzero => int32 data
    }
}

// ---------------- GEMM1 via mma.sync bf16 split + fused s1 ----------------
// grid (ceil(N/128), 8 heads), block 256 (8 warps). Warp tile 32x32.
// D = Ahi*Bhi + Alo*Bhi + Ahi*Blo  (split-bf16 fp32 emulation)
// smem (dynamic, bytes):
#define OFF_AHI 0        // [128][72] bf16 = 18432
#define OFF_ALO 18432    // 18432
#define OFF_BHI 36864    // [64][72] bf16 = 9216
#define OFF_BLO 46080    // 9216
#define OFF_PS  55296    // float[256]: [0..127] sa, [128..255] sb
#define G1_SMEM 56320
#define ASTR 72
#define BSTR 72

__global__ void __launch_bounds__(256)
gemm1_mma_kernel(const float* __restrict__ A, const float* __restrict__ W,
                 const float* __restrict__ a)
{
    extern __shared__ __align__(16) unsigned char smem[];
    __nv_bfloat16* As_hi = (__nv_bfloat16*)(smem + OFF_AHI);
    __nv_bfloat16* As_lo = (__nv_bfloat16*)(smem + OFF_ALO);
    __nv_bfloat16* Bt_hi = (__nv_bfloat16*)(smem + OFF_BHI);
    __nv_bfloat16* Bt_lo = (__nv_bfloat16*)(smem + OFF_BLO);
    float* ps = (float*)(smem + OFF_PS);

    const int head = blockIdx.y;
    const int row0 = blockIdx.x * 128;
    const int tid = threadIdx.x;
    const int warp = tid >> 5, lane = tid & 31;
    const int gid = lane >> 2, tig = lane & 3;
    const int mr = (warp >> 1) * 32;    // warp row base
    const int nc = (warp & 1) * 32;     // warp col base
    const float* Bg = W + (size_t)head * NFEAT * NHID;

    float d[2][4][4];
#pragma unroll
    for (int mt = 0; mt < 2; mt++)
#pragma unroll
        for (int nt = 0; nt < 4; nt++)
#pragma unroll
            for (int i = 0; i < 4; i++) d[mt][nt][i] = 0.f;

    if (tid < 128) { ps[tid] = 0.f; ps[128 + tid] = 0.f; }

    for (int c = 0; c < 4; c++) {       // K chunks of 64
        // load A chunk 128x64 (fp32 -> hi/lo bf16)
#pragma unroll
        for (int l = 0; l < 16; l++) {
            int i = tid + l * 256;       // 0..4095 float2 units
            int r = i >> 5, kp = i & 31;
            int gr = row0 + r;
            float2 f = make_float2(0.f, 0.f);
            if (gr < N_NODES) f = *(const float2*)&A[(size_t)gr * NFEAT + c * 64 + kp * 2];
            __nv_bfloat16 hx = __float2bfloat16(f.x), hy = __float2bfloat16(f.y);
            float rx = f.x - __bfloat162float(hx), ry = f.y - __bfloat162float(hy);
            __nv_bfloat162 hi2; hi2.x = hx; hi2.y = hy;
            __nv_bfloat162 lo2; lo2.x = __float2bfloat16(rx); lo2.y = __float2bfloat16(ry);
            u32 hv, lv; memcpy(&hv, &hi2, 4); memcpy(&lv, &lo2, 4);
            *(u32*)&As_hi[r * ASTR + kp * 2] = hv;
            *(u32*)&As_lo[r * ASTR + kp * 2] = lv;
        }
        // load B chunk 64x64, transposed to Bt[n][k]
#pragma unroll
        for (int l = 0; l < 16; l++) {
            int i = tid + l * 256;       // 0..4095
            int kk = i >> 6, n = i & 63;
            float w = Bg[(size_t)(c * 64 + kk) * NHID + n];
            __nv_bfloat16 hi = __float2bfloat16(w);
            Bt_hi[n * BSTR + kk] = hi;
            Bt_lo[n * BSTR + kk] = __float2bfloat16(w - __bfloat162float(hi));
        }
        __syncthreads();

#pragma unroll
        for (int s = 0; s < 4; s++) {    // k16 steps
            u32 ahi[2][4], alo[2][4], bhi[4][2], blo[4][2];
            int kb = s * 16 + tig * 2;
#pragma unroll
            for (int mt = 0; mt < 2; mt++) {
                int r0 = mr + mt * 16 + gid;
                ahi[mt][0] = *(const u32*)&As_hi[r0 * ASTR + kb];
                ahi[mt][1] = *(const u32*)&As_hi[(r0 + 8) * ASTR + kb];
                ahi[mt][2] = *(const u32*)&As_hi[r0 * ASTR + kb + 8];
                ahi[mt][3] = *(const u32*)&As_hi[(r0 + 8) * ASTR + kb + 8];
                alo[mt][0] = *(const u32*)&As_lo[r0 * ASTR + kb];
                alo[mt][1] = *(const u32*)&As_lo[(r0 + 8) * ASTR + kb];
                alo[mt][2] = *(const u32*)&As_lo[r0 * ASTR + kb + 8];
                alo[mt][3] = *(const u32*)&As_lo[(r0 + 8) * ASTR + kb + 8];
            }
#pragma unroll
            for (int nt = 0; nt < 4; nt++) {
                int n0 = nc + nt * 8 + gid;
                bhi[nt][0] = *(const u32*)&Bt_hi[n0 * BSTR + kb];
                bhi[nt][1] = *(const u32*)&Bt_hi[n0 * BSTR + kb + 8];
                blo[nt][0] = *(const u32*)&Bt_lo[n0 * BSTR + kb];
                blo[nt][1] = *(const u32*)&Bt_lo[n0 * BSTR + kb + 8];
            }
#pragma unroll
            for (int mt = 0; mt < 2; mt++)
#pragma unroll
                for (int nt = 0; nt < 4; nt++) {
                    mma16816(d[mt][nt], ahi[mt], bhi[nt]);
                    mma16816(d[mt][nt], alo[mt], bhi[nt]);
                    mma16816(d[mt][nt], ahi[mt], blo[nt]);
                }
        }
        __syncthreads();
    }

    // ---- epilogue: store h, fused s1 dots ----
    const float* ak = a + (size_t)head * 2 * NHID;
    float a1v[4][2], a2v[4][2];
#pragma unroll
    for (int nt = 0; nt < 4; nt++) {
        int cn = nc + nt * 8 + tig * 2;
        a1v[nt][0] = ak[cn];     a1v[nt][1] = ak[cn + 1];
        a2v[nt][0] = ak[64 + cn]; a2v[nt][1] = ak[64 + cn + 1];
    }
    float psa[2][2] = {{0.f,0.f},{0.f,0.f}}, psb[2][2] = {{0.f,0.f},{0.f,0.f}};
#pragma unroll
    for (int mt = 0; mt < 2; mt++) {
        int rA = mr + mt * 16 + gid;
        int rB = rA + 8;
        bool okA = (row0 + rA < N_NODES), okB = (row0 + rB < N_NODES);
#pragma unroll
        for (int nt = 0; nt < 4; nt++) {
            int cn = nc + nt * 8 + tig * 2;
            float v0 = d[mt][nt][0], v1 = d[mt][nt][1];
            float v2 = d[mt][nt][2], v3 = d[mt][nt][3];
            if (okA) *(float2*)&g_h[(size_t)(row0 + rA) * NH_TOT + head * NHID + cn] = make_float2(v0, v1);
            if (okB) *(float2*)&g_h[(size_t)(row0 + rB) * NH_TOT + head * NHID + cn] = make_float2(v2, v3);
            psa[mt][0] += v0 * a1v[nt][0] + v1 * a1v[nt][1];
            psa[mt][1] += v2 * a1v[nt][0] + v3 * a1v[nt][1];
            psb[mt][0] += v0 * a2v[nt][0] + v1 * a2v[nt][1];
            psb[mt][1] += v2 * a2v[nt][0] + v3 * a2v[nt][1];
        }
    }
    // reduce over tig (quad lanes share rows)
#pragma unroll
    for (int mt = 0; mt < 2; mt++)
#pragma unroll
        for (int half = 0; half < 2; half++) {
#pragma unroll
            for (int o = 1; o < 4; o <<= 1) {
                psa[mt][half] += __shfl_xor_sync(0xffffffffu, psa[mt][half], o);
                psb[mt][half] += __shfl_xor_sync(0xffffffffu, psb[mt][half], o);
            }
        }
    if (tig == 0) {
#pragma unroll
        for (int mt = 0; mt < 2; mt++) {
            int rA = mr + mt * 16 + gid, rB = rA + 8;
            atomicAdd(&ps[rA], psa[mt][0]);
            atomicAdd(&ps[rB], psa[mt][1]);
            atomicAdd(&ps[128 + rA], psb[mt][0]);
            atomicAdd(&ps[128 + rB], psb[mt][1]);
        }
    }
    __syncthreads();
    if (tid < 128 && row0 + tid < N_NODES) {
        g_ssrc[(size_t)(row0 + tid) * NHEADS + head] = ps[tid];
        g_sdstT[(size_t)head * N_NODES + row0 + tid] = ps[128 + tid];
    }
}

// ---------------- CSR build ----------------
__global__ void hist_kernel(const void* __restrict__ ei) {
    int e = blockIdx.x * blockDim.x + threadIdx.x;
    if (e >= N_EDGES) return;
    atomicAdd(&g_counts[edge_src(ei, e)], 1);
}

__global__ void chunk_sums_kernel() {
    __shared__ int sh[512];
    int i = blockIdx.x * 512 + threadIdx.x;
    sh[threadIdx.x] = (i < N_NODES) ? g_counts[i] : 0;
    __syncthreads();
#pragma unroll
    for (int s = 256; s > 0; s >>= 1) {
        if (threadIdx.x < s) sh[threadIdx.x] += sh[threadIdx.x + s];
        __syncthreads();
    }
    if (threadIdx.x == 0) g_partials[blockIdx.x] = sh[0];
}

__global__ void scan_partials_kernel(int n) {
    __shared__ int sh[256];
    int v = (threadIdx.x < n) ? g_partials[threadIdx.x] : 0;
    sh[threadIdx.x] = v;
    __syncthreads();
#pragma unroll
    for (int d = 1; d < 256; d <<= 1) {
        int t = (threadIdx.x >= d) ? sh[threadIdx.x - d] : 0;
        __syncthreads();
        sh[threadIdx.x] += t;
        __syncthreads();
    }
    if (threadIdx.x < n) g_partials[threadIdx.x] = sh[threadIdx.x] - v;  // exclusive
}

__global__ void scan_chunks_kernel() {
    __shared__ int sh[512];
    int i = blockIdx.x * 512 + threadIdx.x;
    int v = (i < N_NODES) ? g_counts[i] : 0;
    sh[threadIdx.x] = v;
    __syncthreads();
#pragma unroll
    for (int d = 1; d < 512; d <<= 1) {
        int t = (threadIdx.x >= d) ? sh[threadIdx.x - d] : 0;
        __syncthreads();
        sh[threadIdx.x] += t;
        __syncthreads();
    }
    int incl = sh[threadIdx.x];
    if (i < N_NODES) g_rowptr[i] = g_partials[blockIdx.x] + incl - v;
    if (i == N_NODES - 1) g_rowptr[N_NODES] = g_partials[blockIdx.x] + incl;
}

__global__ void scatter_kernel(const void* __restrict__ ei) {
    int e = blockIdx.x * blockDim.x + threadIdx.x;
    if (e >= N_EDGES) return;
    int s = edge_src(ei, e);
    int d = edge_dst(ei, e);
    int pos = g_rowptr[s] + atomicAdd(&g_fill[s], 1);
    g_csr[pos] = d;
}

// ---------------- agg1: per (node, head) aggregation (fp32) ----
__global__ __launch_bounds__(256) void agg1_kernel() {
    int lane = threadIdx.x & 31;
    int n = blockIdx.x * 8 + (threadIdx.x >> 5);
    if (n >= N_NODES) return;
    int k = blockIdx.y;
    int beg = g_rowptr[n], end = g_rowptr[n + 1];
    float ssrc = g_ssrc[(size_t)n * NHEADS + k];
    const float* sdT = g_sdstT + (size_t)k * N_NODES;
    float acc0 = 0.f, acc1 = 0.f, rs = 0.f;

    for (int c0 = beg; c0 < end; c0 += 32) {
        int m = end - c0; if (m > 32) m = 32;
        int dst = 0; float e = 0.f;
        if (lane < m) {
            dst = g_csr[c0 + lane];
            float z = ssrc + sdT[dst];
            float lr = fmaxf(z, ALPHA * z);
            e = __expf(-lr);
        }
        for (int j = 0; j < m; j++) {
            float ej = __shfl_sync(0xffffffffu, e, j);
            int   dj = __shfl_sync(0xffffffffu, dst, j);
            const float* hr = g_h + (size_t)dj * NH_TOT + k * NHID;
            acc0 += ej * hr[lane];
            acc1 += ej * hr[lane + 32];
            rs += ej;
        }
    }
    float inv = 1.f / (rs + EPSG);
    float v0 = acc0 * inv, v1 = acc1 * inv;
    v0 = (v0 > 0.f) ? v0 : expm1f(v0);
    v1 = (v1 > 0.f) ? v1 : expm1f(v1);
    g_x[(size_t)n * NH_TOT + k * NHID + lane] = v0;
    g_x[(size_t)n * NH_TOT + k * NHID + lane + 32] = v1;
}

// ---------------- GEMM2: h2 = x @ W_out (512 -> 97), f32x2 packed ----------------
__global__ __launch_bounds__(256) void gemm2_kernel(const float* __restrict__ Wo) {
    __shared__ float xs[64][68];   // [k][row]
    int c = threadIdx.x;           // 0..127 (active < 97)
    int ty = threadIdx.y;          // 0..1
    int tid = ty * 128 + c;
    int row0 = blockIdx.x * 64;
    bool act = (c < NCLASS);

    ull acc[16];
#pragma unroll
    for (int m = 0; m < 16; m++) acc[m] = 0ull;

    for (int k0 = 0; k0 < NH_TOT; k0 += 64) {
#pragma unroll
        for (int l = 0; l < 4; l++) {
            int idx = tid + l * 256;       // 0..1023
            int r = idx & 63, q = idx >> 6; // q 0..15
            float4 v = make_float4(0.f, 0.f, 0.f, 0.f);
            if (row0 + r < N_NODES)
                v = *(const float4*)&g_x[(size_t)(row0 + r) * NH_TOT + k0 + q * 4];
            xs[q * 4 + 0][r] = v.x; xs[q * 4 + 1][r] = v.y;
            xs[q * 4 + 2][r] = v.z; xs[q * 4 + 3][r] = v.w;
        }
        __syncthreads();
#pragma unroll 4
        for (int k = 0; k < 64; k++) {
            float w = act ? Wo[(size_t)(k0 + k) * NCLASS + c] : 0.f;
            ull wp = pack2(w, w);
            const ulonglong2* xr = (const ulonglong2*)&xs[k][ty * 32];
#pragma unroll
            for (int m = 0; m < 8; m++) {
                ulonglong2 xv = xr[m];
                ffma2(acc[2 * m], xv.x, wp);
                ffma2(acc[2 * m + 1], xv.y, wp);
            }
        }
        __syncthreads();
    }
    if (act) {
#pragma unroll
        for (int m = 0; m < 16; m++) {
            float2 v = unpack2(acc[m]);
            int base = (m & 1) ? (ty * 32 + (m >> 1) * 4 + 2) : (ty * 32 + (m >> 1) * 4);
            int gr0 = row0 + base, gr1 = gr0 + 1;
            if (gr0 < N_NODES) g_h2[(size_t)gr0 * NCLASS + c] = v.x;
            if (gr1 < N_NODES) g_h2[(size_t)gr1 * NCLASS + c] = v.y;
        }
    }
}

// ---------------- s2: per-node dots with a_out halves ----------------
__global__ __launch_bounds__(256) void s2_kernel(const float* __restrict__ ao) {
    int lane = threadIdx.x & 31;
    int n = blockIdx.x * 8 + (threadIdx.x >> 5);
    if (n >= N_NODES) return;
    const float* hr = g_h2 + (size_t)n * NCLASS;
    float sa = 0.f, sb = 0.f;
#pragma unroll
    for (int q = 0; q < 4; q++) {
        int cc = lane + q * 32;
        if (cc < NCLASS) {
            float v = hr[cc];
            sa += v * ao[cc];
            sb += v * ao[NCLASS + cc];
        }
    }
#pragma unroll
    for (int o = 16; o; o >>= 1) {
        sa += __shfl_down_sync(0xffffffffu, sa, o);
        sb += __shfl_down_sync(0xffffffffu, sb, o);
    }
    if (lane == 0) { g_s2src[n] = sa; g_s2dst[n] = sb; }
}

// ---------------- agg2: aggregation + elu + log_softmax ----------------
__global__ __launch_bounds__(256) void agg2_kernel(float* __restrict__ out) {
    int lane = threadIdx.x & 31;
    int n = blockIdx.x * 8 + (threadIdx.x >> 5);
    if (n >= N_NODES) return;
    int beg = g_rowptr[n], end = g_rowptr[n + 1];
    float ssrc = g_s2src[n];
    float acc[4] = {0.f, 0.f, 0.f, 0.f};
    float rs = 0.f;

    for (int c0 = beg; c0 < end; c0 += 32) {
        int m = end - c0; if (m > 32) m = 32;
        int dst = 0; float e = 0.f;
        if (lane < m) {
            dst = g_csr[c0 + lane];
            float z = ssrc + g_s2dst[dst];
            float lr = fmaxf(z, ALPHA * z);
            e = __expf(-lr);
        }
        for (int j = 0; j < m; j++) {
            float ej = __shfl_sync(0xffffffffu, e, j);
            int   dj = __shfl_sync(0xffffffffu, dst, j);
            const float* hr = g_h2 + (size_t)dj * NCLASS;
#pragma unroll
            for (int q = 0; q < 4; q++) {
                int cc = lane + q * 32;
                if (cc < NCLASS) acc[q] += ej * hr[cc];
            }
            rs += ej;
        }
    }
    float inv = 1.f / (rs + EPSG);
    float v[4];
    float mx = -INFINITY;
#pragma unroll
    for (int q = 0; q < 4; q++) {
        int cc = lane + q * 32;
        if (cc < NCLASS) {
            float t = acc[q] * inv;
            t = (t > 0.f) ? t : expm1f(t);
            v[q] = t;
            mx = fmaxf(mx, t);
        } else v[q] = -INFINITY;
    }
#pragma unroll
    for (int o = 16; o; o >>= 1) mx = fmaxf(mx, __shfl_xor_sync(0xffffffffu, mx, o));
    float se = 0.f;
#pragma unroll
    for (int q = 0; q < 4; q++) {
        int cc = lane + q * 32;
        if (cc < NCLASS) se += __expf(v[q] - mx);
    }
#pragma unroll
    for (int o = 16; o; o >>= 1) se += __shfl_xor_sync(0xffffffffu, se, o);
    float lse = mx + logf(se);
#pragma unroll
    for (int q = 0; q < 4; q++) {
        int cc = lane + q * 32;
        if (cc < NCLASS) out[(size_t)n * NCLASS + cc] = v[q] - lse;
    }
}

// ---------------- launch ----------------
extern "C" void kernel_launch(void* const* d_in, const int* in_sizes, int n_in,
                              void* d_out, int out_size) {
    const float* features = (const float*)d_in[0];
    const float* W        = (const float*)d_in[1];
    const float* a        = (const float*)d_in[2];
    const float* W_out    = (const float*)d_in[3];
    const float* a_out    = (const float*)d_in[4];
    const void*  ei       = d_in[5];
    float* out            = (float*)d_out;

    cudaFuncSetAttribute(gemm1_mma_kernel,
                         cudaFuncAttributeMaxDynamicSharedMemorySize, G1_SMEM);

    init_kernel<<<(N_NODES + 255) / 256, 256>>>();
    detect_kernel<<<16, 256>>>((const int*)ei);

    gemm1_mma_kernel<<<dim3((N_NODES + 127) / 128, NHEADS), 256, G1_SMEM>>>(features, W, a);

    hist_kernel<<<(N_EDGES + 255) / 256, 256>>>(ei);
    int nchunks = (N_NODES + 511) / 512;   // 196
    chunk_sums_kernel<<<nchunks, 512>>>();
    scan_partials_kernel<<<1, 256>>>(nchunks);
    scan_chunks_kernel<<<nchunks, 512>>>();
    scatter_kernel<<<(N_EDGES + 255) / 256, 256>>>(ei);

    agg1_kernel<<<dim3((N_NODES + 7) / 8, NHEADS), 256>>>();

    gemm2_kernel<<<(N_NODES + 63) / 64, dim3(128, 2)>>>(W_out);
    s2_kernel<<<(N_NODES + 7) / 8, 256>>>(a_out);
    agg2_kernel<<<(N_NODES + 7) / 8, 256>>>(out);
}